// round 6
// baseline (speedup 1.0000x reference)
#include <cuda_runtime.h>
#include <cuda_bf16.h>

#define FULL 0xffffffffu

static __device__ __forceinline__ unsigned long long pk2(float lo, float hi) {
    unsigned long long r;
    asm("mov.b64 %0, {%1,%2};" : "=l"(r) : "f"(lo), "f"(hi));
    return r;
}
static __device__ __forceinline__ void upk2(unsigned long long v, float& lo, float& hi) {
    asm("mov.b64 {%0,%1}, %2;" : "=f"(lo), "=f"(hi) : "l"(v));
}
static __device__ __forceinline__ unsigned long long fma2(unsigned long long a,
                                                          unsigned long long b,
                                                          unsigned long long c) {
    unsigned long long d;
    asm("fma.rn.f32x2 %0,%1,%2,%3;" : "=l"(d) : "l"(a), "l"(b), "l"(c));
    return d;
}
static __device__ __forceinline__ unsigned long long add2(unsigned long long a,
                                                           unsigned long long b) {
    unsigned long long d;
    asm("add.rn.f32x2 %0,%1,%2;" : "=l"(d) : "l"(a), "l"(b));
    return d;
}
static __device__ __forceinline__ unsigned long long mul2(unsigned long long a,
                                                           unsigned long long b) {
    unsigned long long d;
    asm("mul.rn.f32x2 %0,%1,%2;" : "=l"(d) : "l"(a), "l"(b));
    return d;
}

static constexpr int Bb = 256;
static constexpr int Tt = 2048;
static constexpr int Dd = 64;

// scratch: per-batch emission+transition score and valid length
__device__ float s12g[Bb];
__device__ int   Lg[Bb];

// ============================================================================
// Pass 1: one block per batch. Extract labels from one-hot y (warp ballots),
// compute L, s1 (emission) and s2 (transition) scores. Fully parallel over t.
// ============================================================================
__global__ __launch_bounds__(256) void crf_score_kernel(
    const float* __restrict__ p,
    const int*   __restrict__ y,
    const int*   __restrict__ mask,
    const float* __restrict__ trans)
{
    const int b   = blockIdx.x;
    const int tid = threadIdx.x;
    const int w   = tid >> 5;
    const int l   = tid & 31;

    __shared__ short lab[Tt];
    __shared__ float sT[Dd * Dd];
    __shared__ float red[8];
    __shared__ int   Lsh;

    // ---- L = T - sum(mask) ----
    const int4* m4 = reinterpret_cast<const int4*>(mask + (size_t)b * Tt);
    int4 ma = m4[tid], mb = m4[256 + tid];
    int s = ma.x + ma.y + ma.z + ma.w + mb.x + mb.y + mb.z + mb.w;
#pragma unroll
    for (int o = 16; o > 0; o >>= 1) s += __shfl_xor_sync(FULL, s, o);
    if (l == 0) red[w] = (float)s;
    __syncthreads();
    if (tid == 0) {
        int tot = 0;
        for (int j = 0; j < 8; j++) tot += (int)red[j];
        Lsh = Tt - tot;
    }

    // ---- transition matrix to shared ----
    for (int i = tid; i < Dd * Dd; i += 256) sT[i] = trans[i];

    // ---- labels: one warp per timestep, ballot on one-hot ----
    const int2* yB = reinterpret_cast<const int2*>(y + (size_t)b * Tt * Dd);
#pragma unroll 4
    for (int t = w; t < Tt; t += 8) {
        int2 yv = yB[t * 32 + l];
        unsigned bx = __ballot_sync(FULL, yv.x != 0);
        unsigned by = __ballot_sync(FULL, yv.y != 0);
        if (l == 0)
            lab[t] = bx ? (short)(2 * (__ffs(bx) - 1)) : (short)(2 * (__ffs(by) - 1) + 1);
    }
    __syncthreads();

    const int L = Lsh;
    const float* pB = p + (size_t)b * Tt * Dd;
    float acc = 0.f;
#pragma unroll 2
    for (int t = tid; t < Tt; t += 256) {
        int lt = lab[t];
        if (t < L)     acc += pB[t * Dd + lt];
        if (t + 1 < L) acc += sT[lt * Dd + lab[t + 1]];
    }
#pragma unroll
    for (int o = 16; o > 0; o >>= 1) acc += __shfl_xor_sync(FULL, acc, o);
    if (l == 0) red[w] = acc;
    __syncthreads();
    if (tid == 0) {
        float tot = 0.f;
        for (int j = 0; j < 8; j++) tot += red[j];
        s12g[b] = tot;
        Lg[b]   = L;
    }
}

// ============================================================================
// Pass 2: forward recurrence. One block = 4 warps = TWO interleaved batches.
// Lane l owns state columns (2l, 2l+1) packed f32x2; warp w reduces over
// source rows d' in [16w, 16w+16) for both batches (eT registers shared).
// Linear domain with power-of-two renormalization.
// ============================================================================
static constexpr int NT  = 128;
static constexpr int CH  = 8;
static constexpr int NCH = Tt / CH;

__global__ __launch_bounds__(NT) void crf_forward_kernel(
    const float* __restrict__ p,       // [B,T,D]
    const float* __restrict__ trans,   // [D,D]
    float*       __restrict__ out)     // [B]
{
    const int blk = blockIdx.x;
    const int b0  = 2 * blk;
    const int b1  = b0 + 1;
    const int tid = threadIdx.x;
    const int w   = tid >> 5;
    const int l   = tid & 31;

    __shared__ unsigned long long part[2][2][NT];   // [batch][buf][tid]
    __shared__ unsigned long long vdup[2][4][16];   // [batch][warp][dup-col]
    __shared__ float sp[2][2][CH][Dd];              // [batch][buf][t][d]

    const int L0 = Lg[b0];
    const int L1 = Lg[b1];
    const int Lmax = max(L0, L1);

    // expT rows [16w,16w+16), cols (2l,2l+1)
    unsigned long long eT[16];
#pragma unroll
    for (int j = 0; j < 16; j++) {
        float2 tv = reinterpret_cast<const float2*>(trans)[(16 * w + j) * 32 + l];
        eT[j] = pk2(__expf(tv.x), __expf(tv.y));
    }

    const float4* p40 = reinterpret_cast<const float4*>(p + (size_t)b0 * Tt * Dd);
    const float4* p41 = reinterpret_cast<const float4*>(p + (size_t)b1 * Tt * Dd);

    // stage chunks 0,1 of both batches; prefetch chunk 2 into registers
    reinterpret_cast<float4*>(sp[0][0])[tid] = p40[tid];
    reinterpret_cast<float4*>(sp[0][1])[tid] = p40[NT + tid];
    reinterpret_cast<float4*>(sp[1][0])[tid] = p41[tid];
    reinterpret_cast<float4*>(sp[1][1])[tid] = p41[NT + tid];
    float4 pr0 = p40[2 * NT + tid];
    float4 pr1 = p41[2 * NT + tid];
    __syncthreads();

    // ---- t = 0 init ----
    float2 pa = *reinterpret_cast<const float2*>(&sp[0][0][0][2 * l]);
    float2 pb = *reinterpret_cast<const float2*>(&sp[1][0][0][2 * l]);
    float vx0 = __expf(pa.x), vy0 = __expf(pa.y);
    float vx1 = __expf(pb.x), vy1 = __expf(pb.y);
    int kt0 = 0, kt1 = 0;
    int kx0 = 0, kx1 = 0;
    if (l == 0) {
        kx0 = (int)((__float_as_uint(vx0) >> 23) & 255) - 127;
        kx1 = (int)((__float_as_uint(vx1) >> 23) & 255) - 127;
    }
    if ((l >> 3) == w) {
        int base = 2 * (l - 8 * w);
        vdup[0][w][base]     = pk2(vx0, vx0);
        vdup[0][w][base + 1] = pk2(vy0, vy0);
        vdup[1][w][base]     = pk2(vx1, vx1);
        vdup[1][w][base + 1] = pk2(vy1, vy1);
    }
    __syncwarp();

    for (int t = 1; t < Lmax; t++) {
        const int ch = t >> 3, tb = t & 7, cb = ch & 1;

        // chunk boundary: commit held regs (chunk ch+1), fetch chunk ch+2
        if (tb == 0) {
            reinterpret_cast<float4*>(sp[0][cb ^ 1])[tid] = pr0;
            reinterpret_cast<float4*>(sp[1][cb ^ 1])[tid] = pr1;
            int nc = min(ch + 2, NCH - 1);
            pr0 = p40[nc * NT + tid];
            pr1 = p41[nc * NT + tid];
        }

        float2 pt0 = *reinterpret_cast<const float2*>(&sp[0][cb][tb][2 * l]);
        float2 pt1 = *reinterpret_cast<const float2*>(&sp[1][cb][tb][2 * l]);

        // stale exponent corrections folded into exp(p_t)
        int k0 = __shfl_sync(FULL, kx0, 0);
        int k1 = __shfl_sync(FULL, kx1, 0);
        float sc0 = __uint_as_float((unsigned)(127 - k0) << 23);
        float sc1 = __uint_as_float((unsigned)(127 - k1) << 23);
        unsigned long long ep0 = pk2(__expf(pt0.x) * sc0, __expf(pt0.y) * sc0);
        unsigned long long ep1 = pk2(__expf(pt1.x) * sc1, __expf(pt1.y) * sc1);

        // partial matvecs over this warp's 16 source rows, both batches
        unsigned long long A0 = 0, A1 = 0, A2 = 0, A3 = 0;
        unsigned long long B0 = 0, B1 = 0, B2 = 0, B3 = 0;
#pragma unroll
        for (int j = 0; j < 16; j += 4) {
            A0 = fma2(vdup[0][w][j + 0], eT[j + 0], A0);
            B0 = fma2(vdup[1][w][j + 0], eT[j + 0], B0);
            A1 = fma2(vdup[0][w][j + 1], eT[j + 1], A1);
            B1 = fma2(vdup[1][w][j + 1], eT[j + 1], B1);
            A2 = fma2(vdup[0][w][j + 2], eT[j + 2], A2);
            B2 = fma2(vdup[1][w][j + 2], eT[j + 2], B2);
            A3 = fma2(vdup[0][w][j + 3], eT[j + 3], A3);
            B3 = fma2(vdup[1][w][j + 3], eT[j + 3], B3);
        }
        const int buf = t & 1;
        part[0][buf][tid] = add2(add2(A0, A1), add2(A2, A3));
        part[1][buf][tid] = add2(add2(B0, B1), add2(B2, B3));
        __syncthreads();

        // every warp redundantly combines 4 partials -> full new state
        unsigned long long S0 = add2(add2(part[0][buf][l],      part[0][buf][32 + l]),
                                     add2(part[0][buf][64 + l], part[0][buf][96 + l]));
        unsigned long long S1 = add2(add2(part[1][buf][l],      part[1][buf][32 + l]),
                                     add2(part[1][buf][64 + l], part[1][buf][96 + l]));
        unsigned long long V0 = mul2(S0, ep0);
        unsigned long long V1 = mul2(S1, ep1);
        float nx0, ny0, nx1, ny1;
        upk2(V0, nx0, ny0);
        upk2(V1, nx1, ny1);

        // commit only while batch is still valid
        if (t < L0) {
            vx0 = nx0; vy0 = ny0;
            kt0 += k0;
            if (l == 0) kx0 = (int)((__float_as_uint(vx0) >> 23) & 255) - 127;
            if ((l >> 3) == w) {
                int base = 2 * (l - 8 * w);
                vdup[0][w][base]     = pk2(vx0, vx0);
                vdup[0][w][base + 1] = pk2(vy0, vy0);
            }
        }
        if (t < L1) {
            vx1 = nx1; vy1 = ny1;
            kt1 += k1;
            if (l == 0) kx1 = (int)((__float_as_uint(vx1) >> 23) & 255) - 127;
            if ((l >> 3) == w) {
                int base = 2 * (l - 8 * w);
                vdup[1][w][base]     = pk2(vx1, vx1);
                vdup[1][w][base + 1] = pk2(vy1, vy1);
            }
        }
        __syncwarp();
    }

    // ---- finalize: warp 0 handles batch0, warp 1 handles batch1 ----
    if (w == 0) {
        float sumv = vx0 + vy0;
#pragma unroll
        for (int o = 16; o > 0; o >>= 1) sumv += __shfl_xor_sync(FULL, sumv, o);
        if (l == 0)
            out[b0] = logf(sumv) + (float)kt0 * 0.6931471805599453f - s12g[b0];
    } else if (w == 1) {
        float sumv = vx1 + vy1;
#pragma unroll
        for (int o = 16; o > 0; o >>= 1) sumv += __shfl_xor_sync(FULL, sumv, o);
        if (l == 0)
            out[b1] = logf(sumv) + (float)kt1 * 0.6931471805599453f - s12g[b1];
    }
}

extern "C" void kernel_launch(void* const* d_in, const int* in_sizes, int n_in,
                              void* d_out, int out_size) {
    const float* p     = (const float*)d_in[0];
    const int*   y     = (const int*)d_in[1];
    const int*   mask  = (const int*)d_in[2];
    const float* trans = (const float*)d_in[3];
    float* out = (float*)d_out;
    crf_score_kernel<<<Bb, 256>>>(p, y, mask, trans);
    crf_forward_kernel<<<Bb / 2, NT>>>(p, trans, out);
}

// round 7
// speedup vs baseline: 2.3125x; 2.3125x over previous
#include <cuda_runtime.h>
#include <cuda_bf16.h>

#define FULL 0xffffffffu

static __device__ __forceinline__ unsigned long long pk2(float lo, float hi) {
    unsigned long long r;
    asm("mov.b64 %0, {%1,%2};" : "=l"(r) : "f"(lo), "f"(hi));
    return r;
}
static __device__ __forceinline__ void upk2(unsigned long long v, float& lo, float& hi) {
    asm("mov.b64 {%0,%1}, %2;" : "=f"(lo), "=f"(hi) : "l"(v));
}
static __device__ __forceinline__ unsigned long long fma2(unsigned long long a,
                                                          unsigned long long b,
                                                          unsigned long long c) {
    unsigned long long d;
    asm("fma.rn.f32x2 %0,%1,%2,%3;" : "=l"(d) : "l"(a), "l"(b), "l"(c));
    return d;
}
static __device__ __forceinline__ unsigned long long add2(unsigned long long a,
                                                           unsigned long long b) {
    unsigned long long d;
    asm("add.rn.f32x2 %0,%1,%2;" : "=l"(d) : "l"(a), "l"(b));
    return d;
}
static __device__ __forceinline__ unsigned long long mul2(unsigned long long a,
                                                           unsigned long long b) {
    unsigned long long d;
    asm("mul.rn.f32x2 %0,%1,%2;" : "=l"(d) : "l"(a), "l"(b));
    return d;
}

static constexpr int Bb = 256;
static constexpr int Tt = 2048;
static constexpr int Dd = 64;
static constexpr int NSEG = 8;          // score segments per batch
static constexpr int SEGT = Tt / NSEG;  // 256 timesteps per segment

// scratch: per-(batch,segment) score partials (deterministic, no atomics) + lengths
__device__ float s12p[Bb][NSEG];
__device__ int   Lg[Bb];

// ============================================================================
// Pass 1a: valid length per batch.  grid=Bb, 256 threads.
// ============================================================================
__global__ __launch_bounds__(256) void len_kernel(const int* __restrict__ mask) {
    const int b = blockIdx.x, tid = threadIdx.x, w = tid >> 5, l = tid & 31;
    __shared__ int red[8];
    const int4* m4 = reinterpret_cast<const int4*>(mask + (size_t)b * Tt);
    int4 a = m4[tid], c = m4[256 + tid];
    int s = a.x + a.y + a.z + a.w + c.x + c.y + c.z + c.w;
#pragma unroll
    for (int o = 16; o > 0; o >>= 1) s += __shfl_xor_sync(FULL, s, o);
    if (l == 0) red[w] = s;
    __syncthreads();
    if (tid == 0) {
        int tot = 0;
#pragma unroll
        for (int j = 0; j < 8; j++) tot += red[j];
        Lg[b] = Tt - tot;
    }
}

// ============================================================================
// Pass 1b: emission + transition score partial for one (batch, segment).
// grid = Bb*NSEG, 256 threads. Labels from one-hot y via warp ballots.
// Each block writes its OWN slot (deterministic).
// ============================================================================
__global__ __launch_bounds__(256) void score_kernel(
    const float* __restrict__ p,
    const int*   __restrict__ y,
    const float* __restrict__ trans)
{
    const int blk = blockIdx.x;
    const int b = blk >> 3, seg = blk & (NSEG - 1);
    const int tid = threadIdx.x, w = tid >> 5, l = tid & 31;
    const int t0 = seg * SEGT;

    __shared__ short lab[SEGT + 1];
    __shared__ float red[8];

    const int2* yB = reinterpret_cast<const int2*>(y + (size_t)b * Tt * Dd);
    // labels for t0..t0+SEGT (incl. boundary), one warp per timestep
    for (int i = w; i <= SEGT; i += 8) {
        int t = t0 + i;
        if (t < Tt) {  // warp-uniform
            int2 yv = yB[t * 32 + l];
            unsigned bx = __ballot_sync(FULL, yv.x != 0);
            unsigned by = __ballot_sync(FULL, yv.y != 0);
            if (l == 0)
                lab[i] = bx ? (short)(2 * (__ffs(bx) - 1))
                            : (short)(2 * (__ffs(by) - 1) + 1);
        }
    }
    __syncthreads();

    const int L = Lg[b];
    const int t = t0 + tid;
    const int lt = lab[tid];
    float acc = 0.f;
    if (t < L)     acc += __ldg(&p[(size_t)b * Tt * Dd + (size_t)t * Dd + lt]);
    if (t + 1 < L) acc += __ldg(&trans[lt * Dd + lab[tid + 1]]);

#pragma unroll
    for (int o = 16; o > 0; o >>= 1) acc += __shfl_xor_sync(FULL, acc, o);
    if (l == 0) red[w] = acc;
    __syncthreads();
    if (tid == 0) {
        float tot = 0.f;
#pragma unroll
        for (int j = 0; j < 8; j++) tot += red[j];
        s12p[b][seg] = tot;
    }
}

// ============================================================================
// Pass 2: forward recurrence. ONE WARP PER BATCH, fully independent — no
// cross-warp sync at all. Blocks of 64 threads (2 warps = 2 batches), grid 128
// -> ~1 block/SM, 2 active SMSPs/SM, 1 warp each.
// Lane l owns state columns (2l,2l+1) packed f32x2; state broadcast through a
// warp-private duplicated smem array (64 LDS.64 + 64 FFMA2 per step).
// Linear domain with power-of-two renormalization. p staged in 8-step chunks.
// ============================================================================
static constexpr int CH  = 8;
static constexpr int NCH = Tt / CH;

__global__ __launch_bounds__(64) void crf_forward_kernel(
    const float* __restrict__ p,       // [B,T,D]
    const float* __restrict__ trans,   // [D,D]
    float*       __restrict__ out)     // [B]
{
    const int w = threadIdx.x >> 5;
    const int l = threadIdx.x & 31;
    const int b = blockIdx.x * 2 + w;

    __shared__ unsigned long long sh[2][Dd];   // [warp][col] duplicated state {v,v}
    __shared__ float sp[2][2][CH][Dd];         // [warp][buf][t][d] staged p

    const int L = Lg[b];

    // expT: all 64 rows, cols (2l,2l+1), packed in 64 u64 regs
    unsigned long long eT[64];
#pragma unroll
    for (int j = 0; j < 64; j++) {
        float2 tv = reinterpret_cast<const float2*>(trans)[j * 32 + l];
        eT[j] = pk2(__expf(tv.x), __expf(tv.y));
    }

    const float4* p4 = reinterpret_cast<const float4*>(p + (size_t)b * Tt * Dd);

    // stage chunks 0,1; prefetch chunk 2 into registers (per-warp, 4 float4/lane)
    float4* st0 = reinterpret_cast<float4*>(sp[w][0]);
    float4* st1 = reinterpret_cast<float4*>(sp[w][1]);
    float4 prf[4];
#pragma unroll
    for (int j = 0; j < 4; j++) {
        st0[j * 32 + l] = p4[j * 32 + l];
        st1[j * 32 + l] = p4[128 + j * 32 + l];
        prf[j]          = p4[256 + j * 32 + l];
    }
    __syncwarp();

    // ---- t = 0 init ----
    float2 p0 = *reinterpret_cast<const float2*>(&sp[w][0][0][2 * l]);
    float vx = __expf(p0.x);
    float vy = __expf(p0.y);
    int ktot = 0;
    int kx = (int)((__float_as_uint(vx) >> 23) & 255) - 127;  // lane 0's is used
    sh[w][2 * l]     = pk2(vx, vx);
    sh[w][2 * l + 1] = pk2(vy, vy);
    __syncwarp();

    for (int t = 1; t < L; t++) {
        const int ch = t >> 3, tb = t & 7, cb = ch & 1;

        // chunk boundary: commit held regs (chunk ch+1), fetch chunk ch+2
        if (tb == 0) {
            float4* dst = reinterpret_cast<float4*>(sp[w][cb ^ 1]);
#pragma unroll
            for (int j = 0; j < 4; j++) dst[j * 32 + l] = prf[j];
            const int nc = min(ch + 2, NCH - 1);
#pragma unroll
            for (int j = 0; j < 4; j++) prf[j] = p4[nc * 128 + j * 32 + l];
            __syncwarp();
        }

        float2 pt = *reinterpret_cast<const float2*>(&sp[w][cb][tb][2 * l]);

        // stale exponent correction folded into exp(p_t)
        int k = __shfl_sync(FULL, kx, 0);
        ktot += k;
        float sc = __uint_as_float((unsigned)(127 - k) << 23);  // 2^{-k}
        unsigned long long ep2 = pk2(__expf(pt.x) * sc, __expf(pt.y) * sc);

        // full matvec: 64 broadcast LDS.64 + 64 FFMA2, 4 accumulator chains
        unsigned long long a0 = 0, a1 = 0, a2 = 0, a3 = 0;
#pragma unroll
        for (int j = 0; j < 64; j += 4) {
            a0 = fma2(sh[w][j + 0], eT[j + 0], a0);
            a1 = fma2(sh[w][j + 1], eT[j + 1], a1);
            a2 = fma2(sh[w][j + 2], eT[j + 2], a2);
            a3 = fma2(sh[w][j + 3], eT[j + 3], a3);
        }
        unsigned long long S = add2(add2(a0, a1), add2(a2, a3));
        unsigned long long V = mul2(S, ep2);
        upk2(V, vx, vy);

        kx = (int)((__float_as_uint(vx) >> 23) & 255) - 127;

        sh[w][2 * l]     = pk2(vx, vx);
        sh[w][2 * l + 1] = pk2(vy, vy);
        __syncwarp();
    }

    // ---- finalize: logZ = log(sum v) + ktot*ln2 ; subtract scores ----
    float sumv = vx + vy;
#pragma unroll
    for (int o = 16; o > 0; o >>= 1) sumv += __shfl_xor_sync(FULL, sumv, o);
    if (l == 0) {
        float s12 = 0.f;
#pragma unroll
        for (int j = 0; j < NSEG; j++) s12 += s12p[b][j];
        out[b] = logf(sumv) + (float)ktot * 0.6931471805599453f - s12;
    }
}

extern "C" void kernel_launch(void* const* d_in, const int* in_sizes, int n_in,
                              void* d_out, int out_size) {
    const float* p     = (const float*)d_in[0];
    const int*   y     = (const int*)d_in[1];
    const int*   mask  = (const int*)d_in[2];
    const float* trans = (const float*)d_in[3];
    float* out = (float*)d_out;
    len_kernel<<<Bb, 256>>>(mask);
    score_kernel<<<Bb * NSEG, 256>>>(p, y, trans);
    crf_forward_kernel<<<Bb / 2, 64>>>(p, trans, out);
}

// round 8
// speedup vs baseline: 2.3693x; 1.0246x over previous
#include <cuda_runtime.h>
#include <cuda_bf16.h>

#define FULL 0xffffffffu

static __device__ __forceinline__ unsigned long long pk2(float lo, float hi) {
    unsigned long long r;
    asm("mov.b64 %0, {%1,%2};" : "=l"(r) : "f"(lo), "f"(hi));
    return r;
}
static __device__ __forceinline__ void upk2(unsigned long long v, float& lo, float& hi) {
    asm("mov.b64 {%0,%1}, %2;" : "=f"(lo), "=f"(hi) : "l"(v));
}
static __device__ __forceinline__ unsigned long long fma2(unsigned long long a,
                                                          unsigned long long b,
                                                          unsigned long long c) {
    unsigned long long d;
    asm("fma.rn.f32x2 %0,%1,%2,%3;" : "=l"(d) : "l"(a), "l"(b), "l"(c));
    return d;
}
static __device__ __forceinline__ unsigned long long add2(unsigned long long a,
                                                           unsigned long long b) {
    unsigned long long d;
    asm("add.rn.f32x2 %0,%1,%2;" : "=l"(d) : "l"(a), "l"(b));
    return d;
}
static __device__ __forceinline__ unsigned long long mul2(unsigned long long a,
                                                           unsigned long long b) {
    unsigned long long d;
    asm("mul.rn.f32x2 %0,%1,%2;" : "=l"(d) : "l"(a), "l"(b));
    return d;
}

static constexpr int Bb = 256;
static constexpr int Tt = 2048;
static constexpr int Dd = 64;
static constexpr int NSEG = 8;          // score segments per batch
static constexpr int SEGT = Tt / NSEG;  // 256 timesteps per segment

// scratch: per-(batch,segment) score partials (deterministic, no atomics) + lengths
__device__ float s12p[Bb][NSEG];
__device__ int   Lg[Bb];

// ============================================================================
// Pass 1a: valid length per batch.  grid=Bb, 256 threads.
// ============================================================================
__global__ __launch_bounds__(256) void len_kernel(const int* __restrict__ mask) {
    const int b = blockIdx.x, tid = threadIdx.x, w = tid >> 5, l = tid & 31;
    __shared__ int red[8];
    const int4* m4 = reinterpret_cast<const int4*>(mask + (size_t)b * Tt);
    int4 a = m4[tid], c = m4[256 + tid];
    int s = a.x + a.y + a.z + a.w + c.x + c.y + c.z + c.w;
#pragma unroll
    for (int o = 16; o > 0; o >>= 1) s += __shfl_xor_sync(FULL, s, o);
    if (l == 0) red[w] = s;
    __syncthreads();
    if (tid == 0) {
        int tot = 0;
#pragma unroll
        for (int j = 0; j < 8; j++) tot += red[j];
        Lg[b] = Tt - tot;
    }
}

// ============================================================================
// Pass 1b: emission + transition score partial for one (batch, segment).
// grid = Bb*NSEG, 256 threads. Labels from one-hot y via warp ballots.
// Each block writes its OWN slot (deterministic).
// ============================================================================
__global__ __launch_bounds__(256) void score_kernel(
    const float* __restrict__ p,
    const int*   __restrict__ y,
    const float* __restrict__ trans)
{
    const int blk = blockIdx.x;
    const int b = blk >> 3, seg = blk & (NSEG - 1);
    const int tid = threadIdx.x, w = tid >> 5, l = tid & 31;
    const int t0 = seg * SEGT;

    __shared__ short lab[SEGT + 1];
    __shared__ float red[8];

    const int2* yB = reinterpret_cast<const int2*>(y + (size_t)b * Tt * Dd);
    // labels for t0..t0+SEGT (incl. boundary), one warp per timestep
    for (int i = w; i <= SEGT; i += 8) {
        int t = t0 + i;
        if (t < Tt) {  // warp-uniform
            int2 yv = yB[t * 32 + l];
            unsigned bx = __ballot_sync(FULL, yv.x != 0);
            unsigned by = __ballot_sync(FULL, yv.y != 0);
            if (l == 0)
                lab[i] = bx ? (short)(2 * (__ffs(bx) - 1))
                            : (short)(2 * (__ffs(by) - 1) + 1);
        }
    }
    __syncthreads();

    const int L = Lg[b];
    const int t = t0 + tid;
    const int lt = lab[tid];
    float acc = 0.f;
    if (t < L)     acc += __ldg(&p[(size_t)b * Tt * Dd + (size_t)t * Dd + lt]);
    if (t + 1 < L) acc += __ldg(&trans[lt * Dd + lab[tid + 1]]);

#pragma unroll
    for (int o = 16; o > 0; o >>= 1) acc += __shfl_xor_sync(FULL, acc, o);
    if (l == 0) red[w] = acc;
    __syncthreads();
    if (tid == 0) {
        float tot = 0.f;
#pragma unroll
        for (int j = 0; j < 8; j++) tot += red[j];
        s12p[b][seg] = tot;
    }
}

// ============================================================================
// Pass 2: forward recurrence. ONE WARP PER BATCH, fully independent.
// Chain-tightened: LDS.128 state broadcast (32 loads), exponent k read
// directly from sh[0] (no shfl), no per-step __syncwarp (converged warp,
// program-ordered smem; compiler fence only), STS.128 state commit.
// Linear domain with power-of-two renormalization. p staged in 8-step chunks.
// ============================================================================
static constexpr int CH  = 8;
static constexpr int NCH = Tt / CH;

__global__ __launch_bounds__(64) void crf_forward_kernel(
    const float* __restrict__ p,       // [B,T,D]
    const float* __restrict__ trans,   // [D,D]
    float*       __restrict__ out)     // [B]
{
    const int w = threadIdx.x >> 5;
    const int l = threadIdx.x & 31;
    const int b = blockIdx.x * 2 + w;

    __shared__ __align__(16) unsigned long long sh[2][Dd];  // [warp][col] {v,v}
    __shared__ float sp[2][2][CH][Dd];                      // [warp][buf][t][d]

    const int L = Lg[b];

    // expT: all 64 rows, cols (2l,2l+1), packed in 64 u64 regs
    unsigned long long eT[64];
#pragma unroll
    for (int j = 0; j < 64; j++) {
        float2 tv = reinterpret_cast<const float2*>(trans)[j * 32 + l];
        eT[j] = pk2(__expf(tv.x), __expf(tv.y));
    }

    const float4* p4 = reinterpret_cast<const float4*>(p + (size_t)b * Tt * Dd);

    // stage chunks 0,1; prefetch chunk 2 into registers (4 float4/lane)
    float4* st0 = reinterpret_cast<float4*>(sp[w][0]);
    float4* st1 = reinterpret_cast<float4*>(sp[w][1]);
    float4 prf[4];
#pragma unroll
    for (int j = 0; j < 4; j++) {
        st0[j * 32 + l] = p4[j * 32 + l];
        st1[j * 32 + l] = p4[128 + j * 32 + l];
        prf[j]          = p4[256 + j * 32 + l];
    }
    __syncwarp();

    // ---- t = 0 init ----
    float2 p0 = *reinterpret_cast<const float2*>(&sp[w][0][0][2 * l]);
    float vx = __expf(p0.x);
    float vy = __expf(p0.y);
    int ktot = 0;
    {
        ulonglong2 stv;
        stv.x = pk2(vx, vx);
        stv.y = pk2(vy, vy);
        *reinterpret_cast<ulonglong2*>(&sh[w][2 * l]) = stv;
    }
    __syncwarp();

    const ulonglong2* shv = reinterpret_cast<const ulonglong2*>(sh[w]);

    for (int t = 1; t < L; t++) {
        const int ch = t >> 3, tb = t & 7, cb = ch & 1;

        // chunk boundary: commit held regs (chunk ch+1), fetch chunk ch+2
        if (tb == 0) {
            float4* dst = reinterpret_cast<float4*>(sp[w][cb ^ 1]);
#pragma unroll
            for (int j = 0; j < 4; j++) dst[j * 32 + l] = prf[j];
            const int nc = min(ch + 2, NCH - 1);
#pragma unroll
            for (int j = 0; j < 4; j++) prf[j] = p4[nc * 128 + j * 32 + l];
            __syncwarp();
        }

        // off-critical-path: emission exp + renorm scale (k = exponent of v[0])
        float2 pt = *reinterpret_cast<const float2*>(&sp[w][cb][tb][2 * l]);
        unsigned ebits = *reinterpret_cast<const unsigned*>(&sh[w][0]);
        int k = (int)((ebits >> 23) & 255) - 127;
        ktot += k;
        float sc = __uint_as_float((unsigned)(127 - k) << 23);  // 2^{-k}
        unsigned long long ep2 = pk2(__expf(pt.x) * sc, __expf(pt.y) * sc);

        // matvec: 32 broadcast LDS.128 + 64 FFMA2, 4 accumulator chains
        unsigned long long a0 = 0, a1 = 0, a2 = 0, a3 = 0;
#pragma unroll
        for (int j = 0; j < 32; j += 2) {
            ulonglong2 q0 = shv[j + 0];
            ulonglong2 q1 = shv[j + 1];
            a0 = fma2(q0.x, eT[2 * j + 0], a0);
            a1 = fma2(q0.y, eT[2 * j + 1], a1);
            a2 = fma2(q1.x, eT[2 * j + 2], a2);
            a3 = fma2(q1.y, eT[2 * j + 3], a3);
        }
        unsigned long long S = add2(add2(a0, a1), add2(a2, a3));
        unsigned long long V = mul2(S, ep2);
        upk2(V, vx, vy);

        // commit state (STS.128); compiler fence instead of __syncwarp —
        // warp is converged (no divergent branches), smem is program-ordered
        ulonglong2 stv;
        stv.x = pk2(vx, vx);
        stv.y = pk2(vy, vy);
        *reinterpret_cast<ulonglong2*>(&sh[w][2 * l]) = stv;
        asm volatile("" ::: "memory");
    }

    // ---- finalize: logZ = log(sum v) + ktot*ln2 ; subtract scores ----
    float sumv = vx + vy;
#pragma unroll
    for (int o = 16; o > 0; o >>= 1) sumv += __shfl_xor_sync(FULL, sumv, o);
    if (l == 0) {
        float s12 = 0.f;
#pragma unroll
        for (int j = 0; j < NSEG; j++) s12 += s12p[b][j];
        out[b] = logf(sumv) + (float)ktot * 0.6931471805599453f - s12;
    }
}

extern "C" void kernel_launch(void* const* d_in, const int* in_sizes, int n_in,
                              void* d_out, int out_size) {
    const float* p     = (const float*)d_in[0];
    const int*   y     = (const int*)d_in[1];
    const int*   mask  = (const int*)d_in[2];
    const float* trans = (const float*)d_in[3];
    float* out = (float*)d_out;
    len_kernel<<<Bb, 256>>>(mask);
    score_kernel<<<Bb * NSEG, 256>>>(p, y, trans);
    crf_forward_kernel<<<Bb / 2, 64>>>(p, trans, out);
}